// round 1
// baseline (speedup 1.0000x reference)
#include <cuda_runtime.h>
#include <math.h>

// Problem constants (fixed shapes from reference)
#define B_DIM 32
#define T_DIM 4096
#define F_DIM 256
#define NSEQ  (B_DIM * F_DIM)   // 8192 independent sequences

// Precomputed per-timestep coefficients: e_t = a_t * e_{t-1} + c_t * x_t
// coef[t].x = a_t, coef[t].y = c_t. coef[0] = {0,1} so t=0 folds into loop.
__device__ float2 g_coef[T_DIM];

__global__ void ema_init_coef_kernel() {
    int t = blockIdx.x * blockDim.x + threadIdx.x;
    if (t >= T_DIM) return;
    const double alpha = 2.0 / (25.0 + 1.0);
    const double oma   = 1.0 - alpha;
    if (t == 0) {
        g_coef[0] = make_float2(0.0f, 1.0f);
        return;
    }
    double w = 1.0 - pow(oma, (double)t + 1.0);
    if (w < 1e-10) w = 1e-10;
    float a = (float)(oma / w);
    float c = (float)(alpha / w);
    g_coef[t] = make_float2(a, c);
}

#define UNROLL 16

__global__ void __launch_bounds__(32, 8)
ema_scan_kernel(const float* __restrict__ x, float* __restrict__ out) {
    int s = blockIdx.x * blockDim.x + threadIdx.x;   // 0..NSEQ-1
    if (s >= NSEQ) return;
    int b = s >> 8;          // / F_DIM
    int f = s & (F_DIM - 1); // % F_DIM

    size_t base = ((size_t)b * T_DIM) * F_DIM + f;
    const float* __restrict__ px = x + base;
    float* __restrict__ po = out + base;

    float e = 0.0f;

    #pragma unroll 1
    for (int t0 = 0; t0 < T_DIM; t0 += UNROLL) {
        float  xv[UNROLL];
        float2 cf[UNROLL];

        // Front-batched independent global loads (MLP)
        #pragma unroll
        for (int i = 0; i < UNROLL; i++) {
            xv[i] = __ldg(px + (size_t)(t0 + i) * F_DIM);
        }
        // Coefficient loads: uniform across warp, L1-resident broadcast
        #pragma unroll
        for (int i = 0; i < UNROLL; i++) {
            cf[i] = __ldg(&g_coef[t0 + i]);
        }
        // Serial FFMA chain + coalesced stores
        #pragma unroll
        for (int i = 0; i < UNROLL; i++) {
            e = fmaf(cf[i].x, e, cf[i].y * xv[i]);
            po[(size_t)(t0 + i) * F_DIM] = e;
        }
    }
}

extern "C" void kernel_launch(void* const* d_in, const int* in_sizes, int n_in,
                              void* d_out, int out_size) {
    const float* x = (const float*)d_in[0];
    float* out = (float*)d_out;

    ema_init_coef_kernel<<<(T_DIM + 255) / 256, 256>>>();

    dim3 block(32);
    dim3 grid(NSEQ / 32);   // 256 blocks of 1 warp -> spread across all SMs
    ema_scan_kernel<<<grid, block>>>(x, out);
}

// round 2
// speedup vs baseline: 3.2819x; 3.2819x over previous
#include <cuda_runtime.h>

// EMA over x[32, 4096, 256] fp32, adjust=True, period=25.
// Chunked-scan: T=4096 split into 8 chunks of 512; each chunk warp-set starts
// 256 steps early from e=0 (forgetting factor oma^256 ~ 1.2e-9 -> exact to fp32).
// For t >= 207 the adjusted weight w_t == 1.0f in fp32, so warmup and all
// chunks j>=1 use compile-time constant coefficients (pure FFMA chain).
// Chunk 0 runs the exact divided recurrence with off-chain reciprocals.

#define B_DIM  32
#define T_DIM  4096
#define F_DIM  256
#define CHUNK  512
#define NCHUNK (T_DIM / CHUNK)     // 8
#define WARMUP 256
#define UNROLL 16

#define ALPHA_C (2.0f / 26.0f)

__global__ void __launch_bounds__(128, 8)
ema_chunked_kernel(const float* __restrict__ x, float* __restrict__ out) {
    const float alpha = ALPHA_C;
    const float oma   = 1.0f - ALPHA_C;

    int g     = blockIdx.x * blockDim.x + threadIdx.x;
    int lane  = g & 31;
    int w     = g >> 5;                 // warp id: 0..2047
    int f_hi  = w & 7;                  // 8 groups of 32 features
    int chunk = (w >> 3) & (NCHUNK - 1);
    int b     = w >> 6;                 // 0..31
    int f     = f_hi * 32 + lane;

    size_t seq_base = ((size_t)b * T_DIM) * F_DIM + f;
    float* __restrict__ po = out + seq_base + (size_t)chunk * CHUNK * F_DIM;

    float e = 0.0f;

    if (chunk == 0) {
        // Exact recurrence from t=0: e_t = (alpha*x_t + oma*e_{t-1}) / (1 - oma^{t+1})
        // (e_{-1}=0 yields e_0 = x_0 exactly, matching the reference init.)
        const float* __restrict__ px = x + seq_base;
        float p0 = 1.0f;                 // oma^{t0}
        #pragma unroll 1
        for (int t0 = 0; t0 < CHUNK; t0 += UNROLL) {
            float xv[UNROLL], rw[UNROLL];
            #pragma unroll
            for (int i = 0; i < UNROLL; i++)
                xv[i] = __ldg(px + (size_t)i * F_DIM);
            // Off-chain reciprocals: p0 * oma^{i+1} with constant-folded powers.
            float q = 1.0f;
            #pragma unroll
            for (int i = 0; i < UNROLL; i++) {
                q *= oma;                            // compile-time constants
                float wt = 1.0f - p0 * q;            // >= alpha, clamp never hits
                rw[i] = __fdividef(1.0f, wt);
            }
            p0 *= q;                                 // q == oma^UNROLL (const)
            // Critical chain: one FFMA per step (coefs pre-scaled by 1/w).
            #pragma unroll
            for (int i = 0; i < UNROLL; i++) {
                e = fmaf(oma * rw[i], e, (alpha * rw[i]) * xv[i]);
                po[(size_t)i * F_DIM] = e;
            }
            px += (size_t)UNROLL * F_DIM;
            po += (size_t)UNROLL * F_DIM;
        }
    } else {
        // Warmup: 256 steps before the chunk, starting from e=0. All t >= 256
        // here, so w_t == 1.0f exactly in fp32 -> constant coefficients.
        const float* __restrict__ px =
            x + seq_base + ((size_t)chunk * CHUNK - WARMUP) * F_DIM;
        #pragma unroll 1
        for (int t0 = 0; t0 < WARMUP; t0 += UNROLL) {
            float xv[UNROLL];
            #pragma unroll
            for (int i = 0; i < UNROLL; i++)
                xv[i] = __ldg(px + (size_t)i * F_DIM);
            #pragma unroll
            for (int i = 0; i < UNROLL; i++)
                e = fmaf(oma, e, alpha * xv[i]);
            px += (size_t)UNROLL * F_DIM;
        }
        // Main: 512 steps with stores.
        #pragma unroll 1
        for (int t0 = 0; t0 < CHUNK; t0 += UNROLL) {
            float xv[UNROLL];
            #pragma unroll
            for (int i = 0; i < UNROLL; i++)
                xv[i] = __ldg(px + (size_t)i * F_DIM);
            #pragma unroll
            for (int i = 0; i < UNROLL; i++) {
                e = fmaf(oma, e, alpha * xv[i]);
                po[(size_t)i * F_DIM] = e;
            }
            px += (size_t)UNROLL * F_DIM;
            po += (size_t)UNROLL * F_DIM;
        }
    }
}

extern "C" void kernel_launch(void* const* d_in, const int* in_sizes, int n_in,
                              void* d_out, int out_size) {
    const float* x = (const float*)d_in[0];
    float* out = (float*)d_out;

    // 32 (b) * 8 (chunks) * 8 (f-groups) * 32 (lanes) = 65536 threads
    int total = B_DIM * NCHUNK * (F_DIM / 32) * 32;
    ema_chunked_kernel<<<total / 128, 128>>>(x, out);
}

// round 3
// speedup vs baseline: 4.0399x; 1.2310x over previous
#include <cuda_runtime.h>

// EMA over x[32, 4096, 256] fp32, adjust=True, period=25.
// Chunked scan (8 chunks of 512 along T) with 192-step warmup from e=0
// (forgetting factor oma^192 ~ 2e-7, far under the 1e-3 threshold).
// Round-3 change: software-pipelined double-buffered loads so each warp keeps
// 16-32 LDGs continuously in flight instead of load/compute phasing.

#define B_DIM   32
#define T_DIM   4096
#define F_DIM   256
#define CHUNK   512
#define NCHUNK  8
#define WARMUP  192
#define UNROLL  16

#define ALPHA_C (2.0f / 26.0f)
#define OMA_C   (1.0f - ALPHA_C)

__device__ __forceinline__ void load_batch(float (&dst)[UNROLL],
                                           const float* __restrict__ p) {
#pragma unroll
    for (int i = 0; i < UNROLL; i++)
        dst[i] = __ldg(p + (size_t)i * F_DIM);
}

// Constant-coefficient chain (w_t == 1.0f exactly for t >= 207): one FFMA/step.
__device__ __forceinline__ void proc_const(const float (&xv)[UNROLL], float& e,
                                           float* __restrict__ po, bool st) {
#pragma unroll
    for (int i = 0; i < UNROLL; i++) {
        e = fmaf(OMA_C, e, ALPHA_C * xv[i]);
        if (st) po[(size_t)i * F_DIM] = e;
    }
}

// Chunk-0 exact adjusted recurrence: e_t = (a*x_t + oma*e_{t-1}) / (1-oma^{t+1}).
// Reciprocals computed off the critical chain; p0 = oma^{t0} on entry.
__device__ __forceinline__ void proc_adj(const float (&xv)[UNROLL], float& e,
                                         float& p0, float* __restrict__ po) {
    float rw[UNROLL];
    float q = 1.0f;
#pragma unroll
    for (int i = 0; i < UNROLL; i++) {
        q *= OMA_C;                    // compile-time power
        float wt = 1.0f - p0 * q;      // >= alpha, clamp never triggers
        rw[i] = __fdividef(1.0f, wt);
    }
    p0 *= q;
#pragma unroll
    for (int i = 0; i < UNROLL; i++) {
        e = fmaf(OMA_C * rw[i], e, (ALPHA_C * rw[i]) * xv[i]);
        po[(size_t)i * F_DIM] = e;
    }
}

__global__ void __launch_bounds__(128, 6)
ema_pipelined_kernel(const float* __restrict__ x, float* __restrict__ out) {
    int g     = blockIdx.x * blockDim.x + threadIdx.x;
    int lane  = g & 31;
    int w     = g >> 5;                 // warp id 0..2047
    int f_hi  = w & 7;
    int chunk = (w >> 3) & (NCHUNK - 1);
    int b     = w >> 6;
    int f     = f_hi * 32 + lane;

    size_t seq_base = ((size_t)b * T_DIM) * F_DIM + f;
    const size_t STRIDE = (size_t)UNROLL * F_DIM;
    float* __restrict__ po = out + seq_base + (size_t)chunk * CHUNK * F_DIM;
    float e = 0.0f;

    float buf0[UNROLL], buf1[UNROLL];

    if (chunk == 0) {
        const float* __restrict__ px = x + seq_base;
        float p0 = 1.0f;
        load_batch(buf0, px); px += STRIDE;
#pragma unroll 1
        for (int t0 = 0; t0 < CHUNK; t0 += 2 * UNROLL) {
            load_batch(buf1, px); px += STRIDE;
            proc_adj(buf0, e, p0, po); po += STRIDE;
            if (t0 + 2 * UNROLL < CHUNK) { load_batch(buf0, px); px += STRIDE; }
            proc_adj(buf1, e, p0, po); po += STRIDE;
        }
    } else {
        const int TOT = WARMUP + CHUNK;  // 704, multiple of 32
        const float* __restrict__ px =
            x + seq_base + ((size_t)chunk * CHUNK - WARMUP) * F_DIM;
        load_batch(buf0, px); px += STRIDE;
#pragma unroll 1
        for (int t0 = 0; t0 < TOT; t0 += 2 * UNROLL) {
            load_batch(buf1, px); px += STRIDE;
            bool stA = (t0 >= WARMUP);
            proc_const(buf0, e, po, stA);
            if (stA) po += STRIDE;
            if (t0 + 2 * UNROLL < TOT) { load_batch(buf0, px); px += STRIDE; }
            bool stB = (t0 + UNROLL >= WARMUP);
            proc_const(buf1, e, po, stB);
            if (stB) po += STRIDE;
        }
    }
}

extern "C" void kernel_launch(void* const* d_in, const int* in_sizes, int n_in,
                              void* d_out, int out_size) {
    const float* x = (const float*)d_in[0];
    float* out = (float*)d_out;
    int total = B_DIM * NCHUNK * (F_DIM / 32) * 32;   // 65536 threads
    ema_pipelined_kernel<<<total / 128, 128>>>(x, out);
}